// round 7
// baseline (speedup 1.0000x reference)
#include <cuda_runtime.h>
#include <cstdint>

#define B_   4
#define C_   64
#define N_   4096
#define IC_  32
#define RUNS 4
#define RL   1024
#define RL1  1025

// ---------------- device scratch (no allocations allowed) ----------------
__device__ float  d_g[B_ * N_ * C_];          // g_x, layout [b][n][o]
__device__ float  d_a[B_ * N_];
__device__ float  d_p[B_ * N_];
__device__ float  d_qa[B_ * N_];              // 4 sorted runs of 1024, ascending
__device__ int    d_pa[B_ * N_];              // original indices
__device__ float  d_e1[B_ * N_];              // exp(q)
__device__ float  d_e2[B_ * N_];              // exp(0.2 q)
__device__ double d_part1[B_ * 64 * 64];      // per-chunk partials [b][ch][o]
__device__ double d_part2[B_ * 64 * 64];
__device__ double d_off1[B_ * 64 * 64];       // run-local suffix-excl offsets
__device__ double d_off2[B_ * 64 * 64];       // run-local prefix-excl offsets
__device__ float  d_S1[B_ * RUNS * RL1 * C_]; // per-run suffix-incl sums [b][run][k][o]
__device__ float  d_S2[B_ * RUNS * RL1 * C_]; // per-run prefix-excl sums
__device__ float  d_T1[B_ * RUNS * RL1];
__device__ float  d_T2[B_ * RUNS * RL1];

// ---------------- kernel 1: g_x GEMM + a,p projections (prep folded in) -----
// grid (32, B), block 256. Tile: 128 nodes x 64 channels, K split in 2 halves.
__global__ void k_gxap(const float* __restrict__ x, const float* __restrict__ gw,
                       const float* __restrict__ gb,
                       const float* __restrict__ tw, const float* __restrict__ tb,
                       const float* __restrict__ pw, const float* __restrict__ pb,
                       const float* __restrict__ cp) {
    __shared__ float sx[32 * 128];        // [cc][n]
    __shared__ float sw[64 * 68];         // [c][o] padded
    __shared__ float swA[C_], swP[C_], sgb[C_];
    __shared__ float sc[2];
    int tid = threadIdx.x;
    int b = blockIdx.y;
    int n0 = blockIdx.x * 128;
    int tx = tid & 15, ty = tid >> 4;

    for (int idx = tid; idx < C_ * C_; idx += 256) {
        int o = idx >> 6, c = idx & 63;
        sw[c * 68 + o] = gw[o * C_ + c];
    }
    if (tid < C_) {
        float wa = 0.f, wp = 0.f;
        for (int i = 0; i < IC_; ++i) {
            wa += cp[i]       * tw[i * C_ + tid];
            wp += cp[IC_ + i] * pw[i * C_ + tid];
        }
        swA[tid] = wa; swP[tid] = wp; sgb[tid] = gb[tid];
    }
    if (tid == 0) {
        float ca = 0.f, cv = 0.f;
        for (int i = 0; i < IC_; ++i) { ca += cp[i] * tb[i]; cv += cp[IC_ + i] * pb[i]; }
        sc[0] = ca; sc[1] = cv;
    }

    float acc[8][4];
#pragma unroll
    for (int nn = 0; nn < 8; ++nn)
#pragma unroll
        for (int j = 0; j < 4; ++j) acc[nn][j] = 0.f;
    float aa = 0.f, pp = 0.f;

    for (int h = 0; h < 2; ++h) {
        __syncthreads();
        const float4* x4 = (const float4*)x;
        float4* sx4 = (float4*)sx;
        for (int idx = tid; idx < 32 * 32; idx += 256) {
            int cc = idx >> 5, n4 = idx & 31;
            sx4[cc * 32 + n4] = x4[((size_t)(b * C_ + h * 32 + cc) * N_ + n0) / 4 + n4];
        }
        __syncthreads();
#pragma unroll 4
        for (int cc = 0; cc < 32; ++cc) {
            float4 wv = *(const float4*)&sw[(h * 32 + cc) * 68 + tx * 4];
#pragma unroll
            for (int nn = 0; nn < 8; ++nn) {
                float xv = sx[cc * 128 + ty * 8 + nn];
                acc[nn][0] += xv * wv.x;
                acc[nn][1] += xv * wv.y;
                acc[nn][2] += xv * wv.z;
                acc[nn][3] += xv * wv.w;
            }
        }
        if (tid < 128) {
            for (int cc = 0; cc < 32; ++cc) {
                float xv = sx[cc * 128 + tid];
                aa += swA[h * 32 + cc] * xv;
                pp += swP[h * 32 + cc] * xv;
            }
        }
    }
    __syncthreads();
    if (tid < 128) {
        d_a[b * N_ + n0 + tid] = aa + sc[0];
        d_p[b * N_ + n0 + tid] = pp + sc[1];
    }
    float4 bias = *(const float4*)&sgb[tx * 4];
#pragma unroll
    for (int nn = 0; nn < 8; ++nn) {
        float4 v;
        v.x = acc[nn][0] + bias.x;
        v.y = acc[nn][1] + bias.y;
        v.z = acc[nn][2] + bias.z;
        v.w = acc[nn][3] + bias.w;
        *(float4*)&d_g[((size_t)(b * N_ + n0 + ty * 8 + nn)) * C_ + tx * 4] = v;
    }
}

// ---------------- kernel 2: chunk bitonic sort, uint64 keys, full CE util ----
// grid (4, B), block 512. Sorts 1024 elems; key = ordered-float<<32 | index
// (tie-free total order -> deterministic). Each thread does exactly one
// compare-exchange per pass.
__global__ void k_csort() {
    __shared__ unsigned long long s[RL];
    int b = blockIdx.y, ch = blockIdx.x;
    int base = ch * RL;
    for (int t = threadIdx.x; t < RL; t += 512) {
        float v = d_p[b * N_ + base + t];
        unsigned u = __float_as_uint(v);
        u = (u & 0x80000000u) ? ~u : (u | 0x80000000u);
        s[t] = ((unsigned long long)u << 32) | (unsigned)(base + t);
    }
    __syncthreads();
    int w = threadIdx.x;
    for (int k = 2; k <= RL; k <<= 1) {
        for (int j = k >> 1; j > 0; j >>= 1) {
            int i  = ((w & ~(j - 1)) << 1) | (w & (j - 1));
            int p2 = i | j;
            bool up = ((i & k) == 0);
            unsigned long long A = s[i], Bv = s[p2];
            if ((A > Bv) == up) { s[i] = Bv; s[p2] = A; }
            __syncthreads();
        }
    }
    for (int t = threadIdx.x; t < RL; t += 512) {
        unsigned long long key = s[t];
        unsigned u = (unsigned)(key >> 32);
        u = (u & 0x80000000u) ? (u ^ 0x80000000u) : ~u;
        d_qa[b * N_ + base + t] = __uint_as_float(u);
        d_pa[b * N_ + base + t] = (int)(unsigned)(key & 0xffffffffu);
    }
}

// ---------------- kernel 3: per-run exp cache + scalar T scans ---------------
// grid (RUNS, B), block 512, 2 elements/thread.
__global__ void k_tscan() {
    __shared__ double ws1[16], ws2[16], tots[2];
    int b = blockIdx.y, run = blockIdx.x;
    int tid = threadIdx.x, lane = tid & 31, w = tid >> 5;
    int kg = b * N_ + run * RL + tid * 2;
    float q0 = d_qa[kg], q1 = d_qa[kg + 1];
    float e10 = expf(q0), e11 = expf(q1);
    float e20 = expf(0.2f * q0), e21 = expf(0.2f * q1);
    d_e1[kg] = e10; d_e1[kg + 1] = e11;
    d_e2[kg] = e20; d_e2[kg + 1] = e21;
    double s1 = (double)e10 + (double)e11;
    double s2 = (double)e20 + (double)e21;
    double i1 = s1, i2 = s2;
#pragma unroll
    for (int off = 1; off < 32; off <<= 1) {
        double t1 = __shfl_up_sync(0xffffffffu, i1, off);
        double t2 = __shfl_up_sync(0xffffffffu, i2, off);
        if (lane >= off) { i1 += t1; i2 += t2; }
    }
    if (lane == 31) { ws1[w] = i1; ws2[w] = i2; }
    __syncthreads();
    if (tid == 0) {
        double r1 = 0.0, r2 = 0.0;
        for (int ww = 0; ww < 16; ++ww) {
            double t1 = ws1[ww], t2 = ws2[ww];
            ws1[ww] = r1; ws2[ww] = r2;
            r1 += t1; r2 += t2;
        }
        tots[0] = r1; tots[1] = r2;
    }
    __syncthreads();
    double base1 = ws1[w] + (i1 - s1);
    double base2 = ws2[w] + (i2 - s2);
    double tot1 = tots[0], tot2 = tots[1];
    int kt = (b * RUNS + run) * RL1 + tid * 2;
    double pe = base1;
    d_T1[kt]     = (float)(tot1 - pe); pe += (double)e10;
    d_T1[kt + 1] = (float)(tot1 - pe);
    pe = base2;
    d_T2[kt]     = (float)pe; pe += (double)e20;
    d_T2[kt + 1] = (float)pe;
    if (tid == 0) {
        d_T1[(b * RUNS + run) * RL1 + RL] = 0.f;
        d_T2[(b * RUNS + run) * RL1 + RL] = (float)tot2;
    }
}

// term values for sorted index k (global), channel o
__device__ __forceinline__ void term_vals(int b, int k, int o, float& t1, float& t2) {
    int pj = d_pa[b * N_ + k];
    float gv = d_g[((size_t)b * N_ + pj) * C_ + o];
    t1 = d_e1[b * N_ + k] * gv;
    t2 = d_e2[b * N_ + k] * gv;
}

// ---------------- kernel 4: per-chunk partial sums ---------------------------
// grid (64 chunks, B), block 512: o = tid&63, r = tid>>6, 8 k per thread.
// Chunks of 64 never cross run boundaries (1024 % 64 == 0).
__global__ void k_scanA() {
    __shared__ double sh1[512], sh2[512];
    int tid = threadIdx.x;
    int b = blockIdx.y, ch = blockIdx.x;
    int o = tid & 63, r = tid >> 6;
    int k0 = ch * 64 + r * 8;
    double s1 = 0.0, s2 = 0.0;
#pragma unroll
    for (int u = 0; u < 8; ++u) {
        float t1, t2; term_vals(b, k0 + u, o, t1, t2);
        s1 += (double)t1; s2 += (double)t2;
    }
    sh1[tid] = s1; sh2[tid] = s2;
    __syncthreads();
    if (r == 0) {
        double a1 = 0.0, a2 = 0.0;
        for (int rr = 0; rr < 8; ++rr) { a1 += sh1[rr * 64 + o]; a2 += sh2[rr * 64 + o]; }
        d_part1[(b * 64 + ch) * 64 + o] = a1;
        d_part2[(b * 64 + ch) * 64 + o] = a2;
    }
}

// ---------------- kernel 5: run-local chunk-offset scans ---------------------
// 1024 tasks = (b, o, run); 16-lane segmented warp scans, 2 tasks per warp.
// grid 16, block 1024.
__global__ void k_scanB() {
    int tid = threadIdx.x;
    int warp = blockIdx.x * 32 + (tid >> 5);
    int lane = tid & 31;
    int seg = lane >> 4;
    int l = lane & 15;                       // chunk within run
    int task = warp * 2 + seg;               // 0..1023
    int b = task >> 8;
    int o = task & 63;
    int run = (task >> 6) & 3;
    int ch = run * 16 + l;
    double v1 = d_part1[(b * 64 + ch) * 64 + o];
    double v2 = d_part2[(b * 64 + ch) * 64 + o];
    double i1 = v1, i2 = v2;
#pragma unroll
    for (int off = 1; off < 16; off <<= 1) {
        double t1 = __shfl_up_sync(0xffffffffu, i1, off, 16);
        double t2 = __shfl_up_sync(0xffffffffu, i2, off, 16);
        if (l >= off) { i1 += t1; i2 += t2; }
    }
    double tot1 = __shfl_sync(0xffffffffu, i1, 15, 16);
    double tot2 = __shfl_sync(0xffffffffu, i2, 15, 16);
    d_off2[(b * 64 + ch) * 64 + o] = i2 - v2;     // prefix-exclusive within run
    d_off1[(b * 64 + ch) * 64 + o] = tot1 - i1;   // suffix-exclusive within run
    if (l == 0) {
        size_t rb = (size_t)(b * RUNS + run) * RL1 + RL;
        d_S1[rb * C_ + o] = 0.f;
        d_S2[rb * C_ + o] = (float)tot2;
    }
}

// ---------------- kernel 6: write full per-run S1/S2 arrays ------------------
__global__ void k_scanC() {
    __shared__ double sh1[512], sh2[512];
    int tid = threadIdx.x;
    int b = blockIdx.y, ch = blockIdx.x;
    int o = tid & 63, r = tid >> 6;
    int run = ch >> 4;
    int k0 = ch * 64 + r * 8;                 // global k
    int kl0 = (ch & 15) * 64 + r * 8;         // run-local k
    float v1[8], v2[8];
    double t1 = 0.0, t2 = 0.0;
#pragma unroll
    for (int u = 0; u < 8; ++u) {
        term_vals(b, k0 + u, o, v1[u], v2[u]);
        t1 += (double)v1[u]; t2 += (double)v2[u];
    }
    sh1[tid] = t1; sh2[tid] = t2;
    __syncthreads();
    double base1 = d_off1[(b * 64 + ch) * 64 + o];
    for (int rr = r + 1; rr < 8; ++rr) base1 += sh1[rr * 64 + o];
    double base2 = d_off2[(b * 64 + ch) * 64 + o];
    for (int rr = 0; rr < r; ++rr) base2 += sh2[rr * 64 + o];

    size_t rowbase = (size_t)(b * RUNS + run) * RL1;
    double s = base1;                          // suffix-inclusive
#pragma unroll
    for (int u = 7; u >= 0; --u) {
        s += (double)v1[u];
        d_S1[(rowbase + kl0 + u) * C_ + o] = (float)s;
    }
    double sp = base2;                         // prefix-exclusive
#pragma unroll
    for (int u = 0; u < 8; ++u) {
        d_S2[(rowbase + kl0 + u) * C_ + o] = (float)sp;
        sp += (double)v2[u];
    }
}

// ---------------- kernel 7: final attention output ---------------------------
// grid (32, B), block 128: one node i per thread; 4 binary searches (per run),
// combine 4 runs' S rows; smem transpose for coalesced store.
__global__ void k_final(float* __restrict__ out) {
    __shared__ float sq[N_];                 // 16KB: all 4 sorted runs
    __shared__ float sout[C_ * 128];         // 32KB
    int tid = threadIdx.x;
    int b = blockIdx.y;
    int i0 = blockIdx.x * 128;

    for (int t = tid; t < N_; t += 128) sq[t] = d_qa[b * N_ + t];
    __syncthreads();

    float aa = d_a[b * N_ + i0 + tid];
    float tgt = -aa;
    int kr[RUNS];
#pragma unroll
    for (int run = 0; run < RUNS; ++run) {
        int base = run * RL, lo = 0, cnt = RL;
        while (cnt > 0) {                    // first k with q[k] >= -a_i
            int st = cnt >> 1;
            int mid = lo + st;
            if (sq[base + mid] < tgt) { lo = mid + 1; cnt -= st + 1; }
            else cnt = st;
        }
        kr[run] = lo;
    }
    float e1 = expf(aa), e2 = expf(0.2f * aa);
    float T1s = 0.f, T2s = 0.f;
#pragma unroll
    for (int run = 0; run < RUNS; ++run) {
        int kt = (b * RUNS + run) * RL1 + kr[run];
        T1s += d_T1[kt];
        T2s += d_T2[kt];
    }
    float Z = e1 * T1s + e2 * T2s;
    float w1 = e1 / Z, w2 = e2 / Z;

    const float4* s1p[RUNS];
    const float4* s2p[RUNS];
#pragma unroll
    for (int run = 0; run < RUNS; ++run) {
        size_t row = ((size_t)(b * RUNS + run) * RL1 + kr[run]) * C_;
        s1p[run] = (const float4*)&d_S1[row];
        s2p[run] = (const float4*)&d_S2[row];
    }
#pragma unroll
    for (int o4 = 0; o4 < 16; ++o4) {
        float vx = 0.f, vy = 0.f, vz = 0.f, vw = 0.f;
#pragma unroll
        for (int run = 0; run < RUNS; ++run) {
            float4 A = s1p[run][o4], Bv = s2p[run][o4];
            vx += w1 * A.x + w2 * Bv.x;
            vy += w1 * A.y + w2 * Bv.y;
            vz += w1 * A.z + w2 * Bv.z;
            vw += w1 * A.w + w2 * Bv.w;
        }
        sout[(o4 * 4 + 0) * 128 + tid] = vx;
        sout[(o4 * 4 + 1) * 128 + tid] = vy;
        sout[(o4 * 4 + 2) * 128 + tid] = vz;
        sout[(o4 * 4 + 3) * 128 + tid] = vw;
    }
    __syncthreads();
    float* outp = out + (size_t)b * C_ * N_;
    for (int idx = tid; idx < C_ * 128; idx += 128) {
        int o = idx >> 7, il = idx & 127;
        outp[(size_t)o * N_ + i0 + il] = sout[idx];
    }
}

// ---------------- kernel 8: C_k term, zero-skip fused ------------------------
// grid 128, block 256; A-tile = 32 Ck rows x 64 j. Per j-tile: load A, test
// nonzero via __syncthreads_or; only then load g and FMA (all 4 batches reuse
// the A tile). Zero Ck degenerates to a single clean 64MB stream with no
// stores. out += sum_j Ck[i,j] * g[b,j,o].
__global__ void k_ckgemm(const float* __restrict__ Ck, float* __restrict__ out) {
    __shared__ float Ash[32][65];
    __shared__ float Bsh[64][64];
    int t = threadIdx.x;
    int i0 = blockIdx.x * 32;
    int ti = t >> 4, to = t & 15;            // ti: 2 i-rows, to: 4 o-cols
    float acc[4][2][4];
#pragma unroll
    for (int bb = 0; bb < 4; ++bb)
#pragma unroll
        for (int ii = 0; ii < 2; ++ii)
#pragma unroll
            for (int oo = 0; oo < 4; ++oo) acc[bb][ii][oo] = 0.f;
    bool any = false;

    for (int j0 = 0; j0 < N_; j0 += 64) {
        int nz_local = 0;
        for (int idx = t; idx < 2048; idx += 256) {
            int ii = idx >> 6, jj = idx & 63;
            float v = Ck[(size_t)(i0 + ii) * N_ + j0 + jj];
            Ash[ii][jj] = v;
            nz_local |= (v != 0.f);
        }
        int nz = __syncthreads_or(nz_local);
        if (nz) {
            any = true;
            for (int bb = 0; bb < 4; ++bb) {
                for (int idx = t; idx < 4096; idx += 256) {
                    int jj = idx >> 6, o = idx & 63;
                    Bsh[jj][o] = d_g[((size_t)(bb * N_) + j0 + jj) * C_ + o];
                }
                __syncthreads();
                for (int jj = 0; jj < 64; ++jj) {
                    float a0 = Ash[ti * 2 + 0][jj];
                    float a1 = Ash[ti * 2 + 1][jj];
                    float b0 = Bsh[jj][to * 4 + 0], b1 = Bsh[jj][to * 4 + 1];
                    float b2 = Bsh[jj][to * 4 + 2], b3 = Bsh[jj][to * 4 + 3];
                    acc[bb][0][0] += a0 * b0; acc[bb][0][1] += a0 * b1;
                    acc[bb][0][2] += a0 * b2; acc[bb][0][3] += a0 * b3;
                    acc[bb][1][0] += a1 * b0; acc[bb][1][1] += a1 * b1;
                    acc[bb][1][2] += a1 * b2; acc[bb][1][3] += a1 * b3;
                }
                __syncthreads();
            }
        }
    }
    if (any) {
#pragma unroll
        for (int bb = 0; bb < 4; ++bb)
#pragma unroll
            for (int ii = 0; ii < 2; ++ii)
#pragma unroll
                for (int oo = 0; oo < 4; ++oo)
                    out[((size_t)bb * C_ + to * 4 + oo) * N_ + i0 + ti * 2 + ii]
                        += acc[bb][ii][oo];
    }
}

// ---------------- launch ----------------
extern "C" void kernel_launch(void* const* d_in, const int* in_sizes, int n_in,
                              void* d_out, int out_size) {
    const float* x   = (const float*)d_in[0];
    const float* gw  = (const float*)d_in[1];
    const float* gb  = (const float*)d_in[2];
    const float* tw  = (const float*)d_in[3];
    const float* tb  = (const float*)d_in[4];
    const float* pw  = (const float*)d_in[5];
    const float* pb  = (const float*)d_in[6];
    const float* cp  = (const float*)d_in[7];
    const float* Ck  = (const float*)d_in[8];
    float* out = (float*)d_out;

    k_gxap<<<dim3(32, B_), 256>>>(x, gw, gb, tw, tb, pw, pb, cp);
    k_csort<<<dim3(RUNS, B_), 512>>>();
    k_tscan<<<dim3(RUNS, B_), 512>>>();
    k_scanA<<<dim3(64, B_), 512>>>();
    k_scanB<<<16, 1024>>>();
    k_scanC<<<dim3(64, B_), 512>>>();
    k_final<<<dim3(32, B_), 128>>>(out);
    k_ckgemm<<<128, 256>>>(Ck, out);
}

// round 8
// speedup vs baseline: 1.4835x; 1.4835x over previous
#include <cuda_runtime.h>
#include <cstdint>

#define B_   4
#define C_   64
#define N_   4096
#define IC_  32
#define N1_  (N_ + 1)
#define NCH  128            // chunks of 32 per batch
#define CHW  32             // chunk width

// ---------------- device scratch (no allocations allowed) ----------------
__device__ float  d_g[B_ * N_ * C_];        // g_x, layout [b][n][o]
__device__ float  d_a[B_ * N_];
__device__ float  d_p[B_ * N_];
__device__ float  d_qa[B_ * N_];            // chunk-sorted (runs of 1024)
__device__ int    d_pa[B_ * N_];
__device__ float  d_qb[B_ * N_];            // runs of 2048
__device__ int    d_pb[B_ * N_];
__device__ float  d_q[B_ * N_];             // fully sorted ascending
__device__ int    d_perm[B_ * N_];
__device__ float  d_e1[B_ * N_];            // exp(q)
__device__ float  d_e2[B_ * N_];            // exp(0.2q)
__device__ double d_part1[B_ * NCH * 64];   // per-chunk partials [b][ch][o]
__device__ double d_part2[B_ * NCH * 64];
__device__ double d_off1[B_ * NCH * 64];    // suffix-exclusive chunk offsets
__device__ double d_off2[B_ * NCH * 64];    // prefix-exclusive chunk offsets
__device__ float  d_S1[B_ * N1_ * C_];      // suffix-inclusive sums [b][k][o]
__device__ float  d_S2[B_ * N1_ * C_];      // prefix-exclusive sums
__device__ float  d_T1[B_ * N1_];
__device__ float  d_T2[B_ * N1_];
__device__ int    d_flag;

// ---------------- kernel 1: g_x GEMM + a,p projections (prep folded in) -----
// grid (32, B), block 256. Tile: 128 nodes x 64 channels, K split in 2 halves.
__global__ void k_gxap(const float* __restrict__ x, const float* __restrict__ gw,
                       const float* __restrict__ gb,
                       const float* __restrict__ tw, const float* __restrict__ tb,
                       const float* __restrict__ pw, const float* __restrict__ pb,
                       const float* __restrict__ cp) {
    __shared__ float sx[32 * 128];        // [cc][n]
    __shared__ float sw[64 * 68];         // [c][o] padded
    __shared__ float swA[C_], swP[C_], sgb[C_];
    __shared__ float sc[2];
    int tid = threadIdx.x;
    int b = blockIdx.y;
    int n0 = blockIdx.x * 128;
    int tx = tid & 15, ty = tid >> 4;

    if (tid == 0 && blockIdx.x == 0 && b == 0) d_flag = 0;   // reset before flag_scan

    for (int idx = tid; idx < C_ * C_; idx += 256) {
        int o = idx >> 6, c = idx & 63;
        sw[c * 68 + o] = gw[o * C_ + c];
    }
    if (tid < C_) {
        float wa = 0.f, wp = 0.f;
        for (int i = 0; i < IC_; ++i) {
            wa += cp[i]       * tw[i * C_ + tid];
            wp += cp[IC_ + i] * pw[i * C_ + tid];
        }
        swA[tid] = wa; swP[tid] = wp; sgb[tid] = gb[tid];
    }
    if (tid == 0) {
        float ca = 0.f, cv = 0.f;
        for (int i = 0; i < IC_; ++i) { ca += cp[i] * tb[i]; cv += cp[IC_ + i] * pb[i]; }
        sc[0] = ca; sc[1] = cv;
    }

    float acc[8][4];
#pragma unroll
    for (int nn = 0; nn < 8; ++nn)
#pragma unroll
        for (int j = 0; j < 4; ++j) acc[nn][j] = 0.f;
    float aa = 0.f, pp = 0.f;

    for (int h = 0; h < 2; ++h) {
        __syncthreads();
        const float4* x4 = (const float4*)x;
        float4* sx4 = (float4*)sx;
        for (int idx = tid; idx < 32 * 32; idx += 256) {
            int cc = idx >> 5, n4 = idx & 31;
            sx4[cc * 32 + n4] = x4[((size_t)(b * C_ + h * 32 + cc) * N_ + n0) / 4 + n4];
        }
        __syncthreads();
#pragma unroll 4
        for (int cc = 0; cc < 32; ++cc) {
            float4 wv = *(const float4*)&sw[(h * 32 + cc) * 68 + tx * 4];
#pragma unroll
            for (int nn = 0; nn < 8; ++nn) {
                float xv = sx[cc * 128 + ty * 8 + nn];
                acc[nn][0] += xv * wv.x;
                acc[nn][1] += xv * wv.y;
                acc[nn][2] += xv * wv.z;
                acc[nn][3] += xv * wv.w;
            }
        }
        if (tid < 128) {
            for (int cc = 0; cc < 32; ++cc) {
                float xv = sx[cc * 128 + tid];
                aa += swA[h * 32 + cc] * xv;
                pp += swP[h * 32 + cc] * xv;
            }
        }
    }
    __syncthreads();
    if (tid < 128) {
        d_a[b * N_ + n0 + tid] = aa + sc[0];
        d_p[b * N_ + n0 + tid] = pp + sc[1];
    }
    float4 bias = *(const float4*)&sgb[tx * 4];
#pragma unroll
    for (int nn = 0; nn < 8; ++nn) {
        float4 v;
        v.x = acc[nn][0] + bias.x;
        v.y = acc[nn][1] + bias.y;
        v.z = acc[nn][2] + bias.z;
        v.w = acc[nn][3] + bias.w;
        *(float4*)&d_g[((size_t)(b * N_ + n0 + ty * 8 + nn)) * C_ + tx * 4] = v;
    }
}

// ---------------- kernel 2a: chunk bitonic sort, u64 keys, full CE util -----
// grid (4, B), block 512. Sorts 1024; key = ordered-float<<32 | index.
__global__ void k_csort() {
    __shared__ unsigned long long s[1024];
    int b = blockIdx.y, ch = blockIdx.x;
    int base = ch * 1024;
    for (int t = threadIdx.x; t < 1024; t += 512) {
        float v = d_p[b * N_ + base + t];
        unsigned u = __float_as_uint(v);
        u = (u & 0x80000000u) ? ~u : (u | 0x80000000u);
        s[t] = ((unsigned long long)u << 32) | (unsigned)(base + t);
    }
    __syncthreads();
    int w = threadIdx.x;
    for (int k = 2; k <= 1024; k <<= 1) {
        for (int j = k >> 1; j > 0; j >>= 1) {
            int i  = ((w & ~(j - 1)) << 1) | (w & (j - 1));
            int p2 = i | j;
            bool up = ((i & k) == 0);
            unsigned long long A = s[i], Bv = s[p2];
            if ((A > Bv) == up) { s[i] = Bv; s[p2] = A; }
            __syncthreads();
        }
    }
    for (int t = threadIdx.x; t < 1024; t += 512) {
        unsigned long long key = s[t];
        unsigned u = (unsigned)(key >> 32);
        u = (u & 0x80000000u) ? (u ^ 0x80000000u) : ~u;
        d_qa[b * N_ + base + t] = __uint_as_float(u);
        d_pa[b * N_ + base + t] = (int)(unsigned)(key & 0xffffffffu);
    }
}

// ---------------- kernel 2b: merge-path merge of adjacent runs ---------------
// Device-global buffers bound IN DEVICE CODE (never pass __device__ symbols as
// kernel args from host). grid (16, B), block 256, one output elem per thread.
template <int RUNLEN>
__global__ void k_merge() {
    const float* qin;  const int* pin;  float* qout;  int* pout;
    if (RUNLEN == 1024) { qin = d_qa; pin = d_pa; qout = d_qb; pout = d_pb; }
    else                { qin = d_qb; pin = d_pb; qout = d_q;  pout = d_perm; }
    const int runLen = RUNLEN;
    int b = blockIdx.y;
    int t = blockIdx.x * 256 + threadIdx.x;
    int pairLen = runLen * 2;
    int pair = t / pairLen;
    int d = t - pair * pairLen;
    const float* A  = qin + (size_t)b * N_ + pair * pairLen;
    const float* Bq = A + runLen;
    const int*   Ai = pin + (size_t)b * N_ + pair * pairLen;
    const int*   Bi = Ai + runLen;
    int lo = d - runLen; if (lo < 0) lo = 0;
    int hi = d < runLen ? d : runLen;
    while (lo < hi) {
        int mid = (lo + hi) >> 1;
        if (A[mid] <= Bq[d - 1 - mid]) lo = mid + 1; else hi = mid;
    }
    int i = lo, j = d - lo;
    bool takeA = (i < runLen) && (j >= runLen || A[i] <= Bq[j]);
    qout[(size_t)b * N_ + pair * pairLen + d] = takeA ? A[i] : Bq[j];
    pout[(size_t)b * N_ + pair * pairLen + d] = takeA ? Ai[i] : Bi[j];
}

// ---------------- kernel 3: exp cache + scalar T scans (warp-shuffle) --------
// grid B, block 512, 8 elements/thread.
__global__ void k_tscan() {
    __shared__ double ws1[16], ws2[16], tots[2];
    int b = blockIdx.x, tid = threadIdx.x;
    int lane = tid & 31, w = tid >> 5;
    int k0 = tid * 8;
    float e1v[8], e2v[8];
    double s1 = 0.0, s2 = 0.0;
#pragma unroll
    for (int u = 0; u < 8; ++u) {
        float qv = d_q[b * N_ + k0 + u];
        e1v[u] = expf(qv);
        e2v[u] = expf(0.2f * qv);
        d_e1[b * N_ + k0 + u] = e1v[u];
        d_e2[b * N_ + k0 + u] = e2v[u];
        s1 += (double)e1v[u]; s2 += (double)e2v[u];
    }
    double i1 = s1, i2 = s2;
#pragma unroll
    for (int off = 1; off < 32; off <<= 1) {
        double t1 = __shfl_up_sync(0xffffffffu, i1, off);
        double t2 = __shfl_up_sync(0xffffffffu, i2, off);
        if (lane >= off) { i1 += t1; i2 += t2; }
    }
    if (lane == 31) { ws1[w] = i1; ws2[w] = i2; }
    __syncthreads();
    if (tid == 0) {
        double r1 = 0.0, r2 = 0.0;
        for (int ww = 0; ww < 16; ++ww) {
            double t1 = ws1[ww], t2 = ws2[ww];
            ws1[ww] = r1; ws2[ww] = r2;
            r1 += t1; r2 += t2;
        }
        tots[0] = r1; tots[1] = r2;
    }
    __syncthreads();
    double base1 = ws1[w] + (i1 - s1);
    double base2 = ws2[w] + (i2 - s2);
    double tot1 = tots[0], tot2 = tots[1];
    double pe = base1;
#pragma unroll
    for (int u = 0; u < 8; ++u) { d_T1[(size_t)b * N1_ + k0 + u] = (float)(tot1 - pe); pe += (double)e1v[u]; }
    pe = base2;
#pragma unroll
    for (int u = 0; u < 8; ++u) { d_T2[(size_t)b * N1_ + k0 + u] = (float)pe; pe += (double)e2v[u]; }
    if (tid == 0) {
        d_T1[(size_t)b * N1_ + N_] = 0.f;
        d_T2[(size_t)b * N1_ + N_] = (float)tot2;
    }
}

// term values for sorted index k, channel o (uses cached exps)
__device__ __forceinline__ void term_vals(int b, int k, int o, float& t1, float& t2) {
    int pj = d_perm[b * N_ + k];
    float gv = d_g[((size_t)b * N_ + pj) * C_ + o];
    t1 = d_e1[b * N_ + k] * gv;
    t2 = d_e2[b * N_ + k] * gv;
}

// ---------------- kernel 4: per-chunk partial sums ---------------------------
// grid (128 chunks, B), block 512: o = tid&63, r = tid>>6, 4 k per thread.
__global__ void k_scanA() {
    __shared__ double sh1[512], sh2[512];
    int tid = threadIdx.x;
    int b = blockIdx.y, ch = blockIdx.x;
    int o = tid & 63, r = tid >> 6;
    int k0 = ch * CHW + r * 4;
    double s1 = 0.0, s2 = 0.0;
#pragma unroll
    for (int u = 0; u < 4; ++u) {
        float t1, t2; term_vals(b, k0 + u, o, t1, t2);
        s1 += (double)t1; s2 += (double)t2;
    }
    sh1[tid] = s1; sh2[tid] = s2;
    __syncthreads();
    if (r == 0) {
        double a1 = 0.0, a2 = 0.0;
        for (int rr = 0; rr < 8; ++rr) { a1 += sh1[rr * 64 + o]; a2 += sh2[rr * 64 + o]; }
        d_part1[(b * NCH + ch) * 64 + o] = a1;
        d_part2[(b * NCH + ch) * 64 + o] = a2;
    }
}

// ---------------- kernel 5: chunk-offset scans, one warp per (b,o) -----------
// grid 8, block 1024 (32 warps): warp id = (b,o); 128 chunks, 4 per lane.
__global__ void k_scanB() {
    int warp = blockIdx.x * 32 + (threadIdx.x >> 5);   // 0..255
    int lane = threadIdx.x & 31;
    int b = warp >> 6, o = warp & 63;

    double v1[4], v2[4];
    double l1 = 0.0, l2 = 0.0;
#pragma unroll
    for (int u = 0; u < 4; ++u) {
        int ch = lane * 4 + u;
        v1[u] = d_part1[(b * NCH + ch) * 64 + o];
        v2[u] = d_part2[(b * NCH + ch) * 64 + o];
        l1 += v1[u]; l2 += v2[u];
    }
    double i1 = l1, i2 = l2;
#pragma unroll
    for (int off = 1; off < 32; off <<= 1) {
        double t1 = __shfl_up_sync(0xffffffffu, i1, off);
        double t2 = __shfl_up_sync(0xffffffffu, i2, off);
        if (lane >= off) { i1 += t1; i2 += t2; }
    }
    double tot1 = __shfl_sync(0xffffffffu, i1, 31);
    double tot2 = __shfl_sync(0xffffffffu, i2, 31);
    double run1 = i1 - l1;              // exclusive prefix of part1 before lane group
    double run2 = i2 - l2;
#pragma unroll
    for (int u = 0; u < 4; ++u) {
        int ch = lane * 4 + u;
        run1 += v1[u];                              // inclusive prefix1 at ch
        d_off1[(b * NCH + ch) * 64 + o] = tot1 - run1;   // suffix-exclusive
        d_off2[(b * NCH + ch) * 64 + o] = run2;          // prefix-exclusive
        run2 += v2[u];
    }
    if (lane == 0) {
        d_S1[((size_t)b * N1_ + N_) * C_ + o] = 0.f;
        d_S2[((size_t)b * N1_ + N_) * C_ + o] = (float)tot2;
    }
}

// ---------------- kernel 6: write full S1/S2 arrays --------------------------
// grid (128 chunks, B), block 512: 4 k per thread.
__global__ void k_scanC() {
    __shared__ double sh1[512], sh2[512];
    int tid = threadIdx.x;
    int b = blockIdx.y, ch = blockIdx.x;
    int o = tid & 63, r = tid >> 6;
    int k0 = ch * CHW + r * 4;
    float v1[4], v2[4];
    double t1 = 0.0, t2 = 0.0;
#pragma unroll
    for (int u = 0; u < 4; ++u) {
        term_vals(b, k0 + u, o, v1[u], v2[u]);
        t1 += (double)v1[u]; t2 += (double)v2[u];
    }
    sh1[tid] = t1; sh2[tid] = t2;
    __syncthreads();
    double base1 = d_off1[(b * NCH + ch) * 64 + o];
    for (int rr = r + 1; rr < 8; ++rr) base1 += sh1[rr * 64 + o];
    double base2 = d_off2[(b * NCH + ch) * 64 + o];
    for (int rr = 0; rr < r; ++rr) base2 += sh2[rr * 64 + o];

    double s = base1;                              // suffix-inclusive
#pragma unroll
    for (int u = 3; u >= 0; --u) {
        s += (double)v1[u];
        d_S1[((size_t)b * N1_ + (k0 + u)) * C_ + o] = (float)s;
    }
    double sp = base2;                             // prefix-exclusive
#pragma unroll
    for (int u = 0; u < 4; ++u) {
        d_S2[((size_t)b * N1_ + (k0 + u)) * C_ + o] = (float)sp;
        sp += (double)v2[u];
    }
}

// ---------------- kernel 7: final attention output ---------------------------
// grid (32, B), block 128: one node i per thread, smem-staged q + transpose
__global__ void k_final(float* __restrict__ out) {
    __shared__ float sq[N_];                 // 16KB
    __shared__ float sout[C_ * 128];         // 32KB
    int tid = threadIdx.x;
    int b = blockIdx.y;
    int i0 = blockIdx.x * 128;

    for (int t = tid; t < N_; t += 128) sq[t] = d_q[b * N_ + t];
    __syncthreads();

    float aa = d_a[b * N_ + i0 + tid];
    float tgt = -aa;
    int lo = 0, cnt = N_;
    while (cnt > 0) {                        // first k with q[k] >= -a_i
        int st = cnt >> 1;
        int mid = lo + st;
        if (sq[mid] < tgt) { lo = mid + 1; cnt -= st + 1; }
        else cnt = st;
    }
    int k = lo;
    float e1 = expf(aa), e2 = expf(0.2f * aa);
    float Z = e1 * d_T1[(size_t)b * N1_ + k] + e2 * d_T2[(size_t)b * N1_ + k];
    float w1 = e1 / Z, w2 = e2 / Z;

    const float4* s1p = (const float4*)&d_S1[((size_t)b * N1_ + k) * C_];
    const float4* s2p = (const float4*)&d_S2[((size_t)b * N1_ + k) * C_];
#pragma unroll
    for (int o4 = 0; o4 < 16; ++o4) {
        float4 A = s1p[o4], Bv = s2p[o4];
        sout[(o4 * 4 + 0) * 128 + tid] = w1 * A.x + w2 * Bv.x;
        sout[(o4 * 4 + 1) * 128 + tid] = w1 * A.y + w2 * Bv.y;
        sout[(o4 * 4 + 2) * 128 + tid] = w1 * A.z + w2 * Bv.z;
        sout[(o4 * 4 + 3) * 128 + tid] = w1 * A.w + w2 * Bv.w;
    }
    __syncthreads();
    float* outp = out + (size_t)b * C_ * N_;
    for (int idx = tid; idx < C_ * 128; idx += 128) {
        int o = idx >> 7, il = idx & 127;
        outp[(size_t)o * N_ + i0 + il] = sout[idx];
    }
}

// ---------------- C_k handling ----------------
__global__ void k_flag_scan(const float* __restrict__ Ck) {
    const float4* f4 = (const float4*)Ck;
    const int total4 = (N_ * N_) / 4;
    int gid = blockIdx.x * blockDim.x + threadIdx.x;
    for (int v = gid; v < total4; v += gridDim.x * blockDim.x) {
        float4 c = f4[v];
        if (c.x != 0.f || c.y != 0.f || c.z != 0.f || c.w != 0.f) d_flag = 1;
    }
}

// cold path: y += C_k @ g_x  (only runs when C_k has any nonzero)
__global__ void k_ckgemm(const float* __restrict__ Ck, float* __restrict__ out) {
    if (!d_flag) return;
    __shared__ float Ash[64][65];
    __shared__ float Bsh[64][64];
    int t = threadIdx.x;          // 256
    int b = blockIdx.y;
    int i0 = blockIdx.x * 64;
    int ti = t >> 4, to = t & 15;
    float acc[4][4];
#pragma unroll
    for (int a = 0; a < 4; ++a)
#pragma unroll
        for (int c = 0; c < 4; ++c) acc[a][c] = 0.f;

    for (int j0 = 0; j0 < N_; j0 += 64) {
        for (int idx = t; idx < 4096; idx += 256) {
            int ii = idx >> 6, jj = idx & 63;
            Ash[ii][jj] = Ck[(size_t)(i0 + ii) * N_ + j0 + jj];
        }
        for (int idx = t; idx < 4096; idx += 256) {
            int jj = idx >> 6, o = idx & 63;
            Bsh[jj][o] = d_g[((size_t)b * N_ + j0 + jj) * C_ + o];
        }
        __syncthreads();
        for (int jj = 0; jj < 64; ++jj) {
            float a0 = Ash[ti * 4 + 0][jj], a1 = Ash[ti * 4 + 1][jj];
            float a2 = Ash[ti * 4 + 2][jj], a3 = Ash[ti * 4 + 3][jj];
            float b0 = Bsh[jj][to * 4 + 0], b1 = Bsh[jj][to * 4 + 1];
            float b2 = Bsh[jj][to * 4 + 2], b3 = Bsh[jj][to * 4 + 3];
            acc[0][0] += a0 * b0; acc[0][1] += a0 * b1; acc[0][2] += a0 * b2; acc[0][3] += a0 * b3;
            acc[1][0] += a1 * b0; acc[1][1] += a1 * b1; acc[1][2] += a1 * b2; acc[1][3] += a1 * b3;
            acc[2][0] += a2 * b0; acc[2][1] += a2 * b1; acc[2][2] += a2 * b2; acc[2][3] += a2 * b3;
            acc[3][0] += a3 * b0; acc[3][1] += a3 * b1; acc[3][2] += a3 * b2; acc[3][3] += a3 * b3;
        }
        __syncthreads();
    }
#pragma unroll
    for (int ii = 0; ii < 4; ++ii)
#pragma unroll
        for (int oo = 0; oo < 4; ++oo)
            out[((size_t)b * C_ + to * 4 + oo) * N_ + i0 + ti * 4 + ii] += acc[ii][oo];
}

// ---------------- launch ----------------
extern "C" void kernel_launch(void* const* d_in, const int* in_sizes, int n_in,
                              void* d_out, int out_size) {
    const float* x   = (const float*)d_in[0];
    const float* gw  = (const float*)d_in[1];
    const float* gb  = (const float*)d_in[2];
    const float* tw  = (const float*)d_in[3];
    const float* tb  = (const float*)d_in[4];
    const float* pw  = (const float*)d_in[5];
    const float* pb  = (const float*)d_in[6];
    const float* cp  = (const float*)d_in[7];
    const float* Ck  = (const float*)d_in[8];
    float* out = (float*)d_out;

    k_gxap<<<dim3(32, B_), 256>>>(x, gw, gb, tw, tb, pw, pb, cp);
    k_flag_scan<<<4096, 256>>>(Ck);
    k_csort<<<dim3(4, B_), 512>>>();
    k_merge<1024><<<dim3(16, B_), 256>>>();
    k_merge<2048><<<dim3(16, B_), 256>>>();
    k_tscan<<<B_, 512>>>();
    k_scanA<<<dim3(NCH, B_), 512>>>();
    k_scanB<<<8, 1024>>>();
    k_scanC<<<dim3(NCH, B_), 512>>>();
    k_final<<<dim3(32, B_), 128>>>(out);
    k_ckgemm<<<dim3(64, B_), 256>>>(Ck, out);
}

// round 12
// speedup vs baseline: 1.8121x; 1.2215x over previous
#include <cuda_runtime.h>
#include <cstdint>

#define B_   4
#define C_   64
#define N_   4096
#define IC_  32
#define N1_  (N_ + 1)
#define NCH  128            // chunks of 32 per batch
#define CHW  32             // chunk width
#define GRID 128
#define TPB  512

// ---------------- device scratch (no allocations allowed) ----------------
__device__ float  d_g[B_ * N_ * C_];        // g_x, layout [b][n][o]
__device__ float  d_a[B_ * N_];
__device__ float  d_p[B_ * N_];
__device__ float  d_qa[B_ * N_];            // chunk-sorted (runs of 1024)
__device__ int    d_pa[B_ * N_];
__device__ float  d_qb[B_ * N_];            // runs of 2048
__device__ int    d_pb[B_ * N_];
__device__ float  d_q[B_ * N_];             // fully sorted ascending
__device__ int    d_perm[B_ * N_];
__device__ float  d_e1[B_ * N_];            // exp(q)
__device__ float  d_e2[B_ * N_];            // exp(0.2q)
__device__ double d_part1[B_ * NCH * 64];
__device__ double d_part2[B_ * NCH * 64];
__device__ double d_off1[B_ * NCH * 64];
__device__ double d_off2[B_ * NCH * 64];
__device__ float  d_S1[B_ * N1_ * C_];
__device__ float  d_S2[B_ * N1_ * C_];
__device__ float  d_T1[B_ * N1_];
__device__ float  d_T2[B_ * N1_];
__device__ int    d_flag;
__device__ unsigned d_barcnt = 0;           // self-resetting barrier state
__device__ unsigned d_bargen = 0;           // monotonically increasing generation

// ---------------- grid barrier (all GRID blocks co-resident) -----------------
// All-atomic, generation-based, self-resetting (replay-safe). The generation is
// read BEFORE arrival; a round cannot complete without this block's arrival, so
// the read can never be stale. Fences order the reset/increment pair (release)
// and the post-spin data reads (acquire).
__device__ __forceinline__ void gsync() {
    __syncthreads();
    if (threadIdx.x == 0) {
        __threadfence();                                  // release my writes
        unsigned gen = atomicAdd(&d_bargen, 0u);          // read gen before arriving
        if (atomicAdd(&d_barcnt, 1u) == GRID - 1) {
            atomicExch(&d_barcnt, 0u);                    // reset for next round
            __threadfence();                              // order reset before release
            atomicAdd(&d_bargen, 1u);                     // release everyone
        } else {
            while (atomicAdd(&d_bargen, 0u) == gen) __nanosleep(64);
        }
        __threadfence();                                  // acquire others' writes
    }
    __syncthreads();
}

// ---------------- shared memory union (48KB exactly) -------------------------
struct GX  { float sx[32 * 128]; float sw[64 * 68]; float swA[C_]; float swP[C_];
             float sgb[C_]; float sc[2]; };
struct SORT{ unsigned long long s[1024]; };
struct TS  { double ws1[16]; double ws2[16]; double tots[2]; };
struct SCN { double sh1[512]; double sh2[512]; };
struct FIN { float sq[N_]; float sout[C_ * 128]; };
struct CKS { float Ash[64][65]; float Bsh[64][64]; };
union  SM  { GX gx; SORT so; TS ts; SCN sc; FIN fi; CKS ck; };

// term values for sorted index k, channel o (uses cached exps)
__device__ __forceinline__ void term_vals(int b, int k, int o, float& t1, float& t2) {
    int pj = d_perm[b * N_ + k];
    float gv = d_g[((size_t)b * N_ + pj) * C_ + o];
    t1 = d_e1[b * N_ + k] * gv;
    t2 = d_e2[b * N_ + k] * gv;
}

// merge-path: one output element per thread (guarded, no early return)
__device__ __forceinline__ void merge_step(const float* __restrict__ qin,
                                           const int* __restrict__ pin,
                                           float* __restrict__ qout,
                                           int* __restrict__ pout,
                                           int runLen, bool doExp) {
    int t = blockIdx.x * TPB + threadIdx.x;
    if (t < B_ * N_) {
        int b = t >> 12;
        int d0 = t & (N_ - 1);
        int pairLen = runLen * 2;
        int pair = d0 / pairLen;
        int d = d0 - pair * pairLen;
        const float* A  = qin + (size_t)b * N_ + pair * pairLen;
        const float* Bq = A + runLen;
        const int*   Ai = pin + (size_t)b * N_ + pair * pairLen;
        const int*   Bi = Ai + runLen;
        int lo = d - runLen; if (lo < 0) lo = 0;
        int hi = d < runLen ? d : runLen;
        while (lo < hi) {
            int mid = (lo + hi) >> 1;
            if (A[mid] <= Bq[d - 1 - mid]) lo = mid + 1; else hi = mid;
        }
        int i = lo, j = d - lo;
        bool takeA = (i < runLen) && (j >= runLen || A[i] <= Bq[j]);
        float qv = takeA ? A[i] : Bq[j];
        qout[(size_t)b * N_ + d0] = qv;
        pout[(size_t)b * N_ + d0] = takeA ? Ai[i] : Bi[j];
        if (doExp) {
            d_e1[b * N_ + d0] = expf(qv);
            d_e2[b * N_ + d0] = expf(0.2f * qv);
        }
    }
}

// scanA task body: per-chunk partial sums for (b, ch)
__device__ __forceinline__ void scanA_task(SCN& s, int b, int ch) {
    int tid = threadIdx.x;
    int o = tid & 63, r = tid >> 6;
    int k0 = ch * CHW + r * 4;
    double s1 = 0.0, s2 = 0.0;
#pragma unroll
    for (int u = 0; u < 4; ++u) {
        float t1, t2; term_vals(b, k0 + u, o, t1, t2);
        s1 += (double)t1; s2 += (double)t2;
    }
    s.sh1[tid] = s1; s.sh2[tid] = s2;
    __syncthreads();
    if (r == 0) {
        double a1 = 0.0, a2 = 0.0;
        for (int rr = 0; rr < 8; ++rr) { a1 += s.sh1[rr * 64 + o]; a2 += s.sh2[rr * 64 + o]; }
        d_part1[(b * NCH + ch) * 64 + o] = a1;
        d_part2[(b * NCH + ch) * 64 + o] = a2;
    }
    __syncthreads();
}

// scanC task body: write S1/S2 rows for (b, ch)
__device__ __forceinline__ void scanC_task(SCN& s, int b, int ch) {
    int tid = threadIdx.x;
    int o = tid & 63, r = tid >> 6;
    int k0 = ch * CHW + r * 4;
    float v1[4], v2[4];
    double t1 = 0.0, t2 = 0.0;
#pragma unroll
    for (int u = 0; u < 4; ++u) {
        term_vals(b, k0 + u, o, v1[u], v2[u]);
        t1 += (double)v1[u]; t2 += (double)v2[u];
    }
    s.sh1[tid] = t1; s.sh2[tid] = t2;
    __syncthreads();
    double base1 = d_off1[(b * NCH + ch) * 64 + o];
    for (int rr = r + 1; rr < 8; ++rr) base1 += s.sh1[rr * 64 + o];
    double base2 = d_off2[(b * NCH + ch) * 64 + o];
    for (int rr = 0; rr < r; ++rr) base2 += s.sh2[rr * 64 + o];

    double ss = base1;
#pragma unroll
    for (int u = 3; u >= 0; --u) {
        ss += (double)v1[u];
        d_S1[((size_t)b * N1_ + (k0 + u)) * C_ + o] = (float)ss;
    }
    double sp = base2;
#pragma unroll
    for (int u = 0; u < 4; ++u) {
        d_S2[((size_t)b * N1_ + (k0 + u)) * C_ + o] = (float)sp;
        sp += (double)v2[u];
    }
    __syncthreads();
}

// ============================ the megakernel =================================
__global__ void __launch_bounds__(TPB, 1)
k_mega(const float* __restrict__ x,  const float* __restrict__ gw,
       const float* __restrict__ gb, const float* __restrict__ tw,
       const float* __restrict__ tb, const float* __restrict__ pw,
       const float* __restrict__ pb, const float* __restrict__ cp,
       const float* __restrict__ Ck, float* __restrict__ out) {
    __shared__ SM sm;
    int tid = threadIdx.x;
    int bid = blockIdx.x;

    // ---------------- P0: g_x GEMM + a,p projections -------------------------
    if (bid == 0 && tid == 0) d_flag = 0;
    {
        int b = bid >> 5, n0 = (bid & 31) * 128;
        int tx = tid & 15, ty = tid >> 4;            // ty: 32 groups of 4 nodes
        for (int idx = tid; idx < C_ * C_; idx += TPB) {
            int o = idx >> 6, c = idx & 63;
            sm.gx.sw[c * 68 + o] = gw[o * C_ + c];
        }
        if (tid < C_) {
            float wa = 0.f, wp = 0.f;
            for (int i = 0; i < IC_; ++i) {
                wa += cp[i]       * tw[i * C_ + tid];
                wp += cp[IC_ + i] * pw[i * C_ + tid];
            }
            sm.gx.swA[tid] = wa; sm.gx.swP[tid] = wp; sm.gx.sgb[tid] = gb[tid];
        }
        if (tid == 0) {
            float ca = 0.f, cv = 0.f;
            for (int i = 0; i < IC_; ++i) { ca += cp[i] * tb[i]; cv += cp[IC_ + i] * pb[i]; }
            sm.gx.sc[0] = ca; sm.gx.sc[1] = cv;
        }
        float acc[4][4];
#pragma unroll
        for (int nn = 0; nn < 4; ++nn)
#pragma unroll
            for (int j = 0; j < 4; ++j) acc[nn][j] = 0.f;
        float aa = 0.f, pp = 0.f;

        for (int h = 0; h < 2; ++h) {
            __syncthreads();
            const float4* x4 = (const float4*)x;
            float4* sx4 = (float4*)sm.gx.sx;
            for (int idx = tid; idx < 1024; idx += TPB) {
                int cc = idx >> 5, n4 = idx & 31;
                sx4[cc * 32 + n4] = x4[((size_t)(b * C_ + h * 32 + cc) * N_ + n0) / 4 + n4];
            }
            __syncthreads();
#pragma unroll 4
            for (int cc = 0; cc < 32; ++cc) {
                float4 wv = *(const float4*)&sm.gx.sw[(h * 32 + cc) * 68 + tx * 4];
#pragma unroll
                for (int nn = 0; nn < 4; ++nn) {
                    float xv = sm.gx.sx[cc * 128 + ty * 4 + nn];
                    acc[nn][0] += xv * wv.x;
                    acc[nn][1] += xv * wv.y;
                    acc[nn][2] += xv * wv.z;
                    acc[nn][3] += xv * wv.w;
                }
            }
            if (tid < 128) {
                for (int cc = 0; cc < 32; ++cc) {
                    float xv = sm.gx.sx[cc * 128 + tid];
                    aa += sm.gx.swA[h * 32 + cc] * xv;
                    pp += sm.gx.swP[h * 32 + cc] * xv;
                }
            }
        }
        __syncthreads();
        if (tid < 128) {
            d_a[b * N_ + n0 + tid] = aa + sm.gx.sc[0];
            d_p[b * N_ + n0 + tid] = pp + sm.gx.sc[1];
        }
        float4 bias = *(const float4*)&sm.gx.sgb[tx * 4];
#pragma unroll
        for (int nn = 0; nn < 4; ++nn) {
            float4 v;
            v.x = acc[nn][0] + bias.x;
            v.y = acc[nn][1] + bias.y;
            v.z = acc[nn][2] + bias.z;
            v.w = acc[nn][3] + bias.w;
            *(float4*)&d_g[((size_t)(b * N_ + n0 + ty * 4 + nn)) * C_ + tx * 4] = v;
        }
    }
    gsync();

    // ---------------- P1: csort (blocks 0-15) || C_k flag scan (16-127) ------
    if (bid < 16) {
        int b = bid >> 2, ch = bid & 3;
        int base = ch * 1024;
        for (int t = tid; t < 1024; t += TPB) {
            float v = d_p[b * N_ + base + t];
            unsigned u = __float_as_uint(v);
            u = (u & 0x80000000u) ? ~u : (u | 0x80000000u);
            sm.so.s[t] = ((unsigned long long)u << 32) | (unsigned)(base + t);
        }
        __syncthreads();
        int w = tid;
        for (int k = 2; k <= 1024; k <<= 1) {
            for (int j = k >> 1; j > 0; j >>= 1) {
                int i  = ((w & ~(j - 1)) << 1) | (w & (j - 1));
                int p2 = i | j;
                bool up = ((i & k) == 0);
                unsigned long long A = sm.so.s[i], Bv = sm.so.s[p2];
                if ((A > Bv) == up) { sm.so.s[i] = Bv; sm.so.s[p2] = A; }
                __syncthreads();
            }
        }
        for (int t = tid; t < 1024; t += TPB) {
            unsigned long long key = sm.so.s[t];
            unsigned u = (unsigned)(key >> 32);
            u = (u & 0x80000000u) ? (u ^ 0x80000000u) : ~u;
            d_qa[b * N_ + base + t] = __uint_as_float(u);
            d_pa[b * N_ + base + t] = (int)(unsigned)(key & 0xffffffffu);
        }
    } else {
        const float4* f4 = (const float4*)Ck;
        int gid = (bid - 16) * TPB + tid;
        int nz = 0;
        for (int v = gid; v < (N_ * N_) / 4; v += 112 * TPB) {
            float4 c = f4[v];
            nz |= (c.x != 0.f) | (c.y != 0.f) | (c.z != 0.f) | (c.w != 0.f);
        }
        if (nz) d_flag = 1;
    }
    gsync();

    // ---------------- P2: merge 1024 -> 2048 ---------------------------------
    merge_step(d_qa, d_pa, d_qb, d_pb, 1024, false);
    gsync();

    // ---------------- P3: merge 2048 -> 4096 (+ exp caches) ------------------
    merge_step(d_qb, d_pb, d_q, d_perm, 2048, true);
    gsync();

    // ---------------- P4: T-scans (blocks 0-3) || scanA (4-127) --------------
    if (bid < B_) {
        int b = bid;
        int lane = tid & 31, w = tid >> 5;
        int k0 = tid * 8;
        float e1v[8], e2v[8];
        double s1 = 0.0, s2 = 0.0;
#pragma unroll
        for (int u = 0; u < 8; ++u) {
            e1v[u] = d_e1[b * N_ + k0 + u];
            e2v[u] = d_e2[b * N_ + k0 + u];
            s1 += (double)e1v[u]; s2 += (double)e2v[u];
        }
        double i1 = s1, i2 = s2;
#pragma unroll
        for (int off = 1; off < 32; off <<= 1) {
            double t1 = __shfl_up_sync(0xffffffffu, i1, off);
            double t2 = __shfl_up_sync(0xffffffffu, i2, off);
            if (lane >= off) { i1 += t1; i2 += t2; }
        }
        if (lane == 31) { sm.ts.ws1[w] = i1; sm.ts.ws2[w] = i2; }
        __syncthreads();
        if (tid == 0) {
            double r1 = 0.0, r2 = 0.0;
            for (int ww = 0; ww < 16; ++ww) {
                double t1 = sm.ts.ws1[ww], t2 = sm.ts.ws2[ww];
                sm.ts.ws1[ww] = r1; sm.ts.ws2[ww] = r2;
                r1 += t1; r2 += t2;
            }
            sm.ts.tots[0] = r1; sm.ts.tots[1] = r2;
        }
        __syncthreads();
        double base1 = sm.ts.ws1[w] + (i1 - s1);
        double base2 = sm.ts.ws2[w] + (i2 - s2);
        double tot1 = sm.ts.tots[0], tot2 = sm.ts.tots[1];
        double pe = base1;
#pragma unroll
        for (int u = 0; u < 8; ++u) {
            d_T1[(size_t)b * N1_ + k0 + u] = (float)(tot1 - pe);
            pe += (double)e1v[u];
        }
        pe = base2;
#pragma unroll
        for (int u = 0; u < 8; ++u) {
            d_T2[(size_t)b * N1_ + k0 + u] = (float)pe;
            pe += (double)e2v[u];
        }
        if (tid == 0) {
            d_T1[(size_t)b * N1_ + N_] = 0.f;
            d_T2[(size_t)b * N1_ + N_] = (float)tot2;
        }
    } else {
        for (int task = bid - 4; task < 512; task += 124)
            scanA_task(sm.sc, task >> 7, task & 127);
    }
    gsync();

    // ---------------- P5: chunk-offset scans (blocks 0-15, warp tasks) -------
    if (bid < 16) {
        int warp = bid * 16 + (tid >> 5);            // 0..255 = (b,o)
        int lane = tid & 31;
        int b = warp >> 6, o = warp & 63;
        double v1[4], v2[4];
        double l1 = 0.0, l2 = 0.0;
#pragma unroll
        for (int u = 0; u < 4; ++u) {
            int ch = lane * 4 + u;
            v1[u] = d_part1[(b * NCH + ch) * 64 + o];
            v2[u] = d_part2[(b * NCH + ch) * 64 + o];
            l1 += v1[u]; l2 += v2[u];
        }
        double i1 = l1, i2 = l2;
#pragma unroll
        for (int off = 1; off < 32; off <<= 1) {
            double t1 = __shfl_up_sync(0xffffffffu, i1, off);
            double t2 = __shfl_up_sync(0xffffffffu, i2, off);
            if (lane >= off) { i1 += t1; i2 += t2; }
        }
        double tot1 = __shfl_sync(0xffffffffu, i1, 31);
        double tot2 = __shfl_sync(0xffffffffu, i2, 31);
        double run1 = i1 - l1;
        double run2 = i2 - l2;
#pragma unroll
        for (int u = 0; u < 4; ++u) {
            int ch = lane * 4 + u;
            run1 += v1[u];
            d_off1[(b * NCH + ch) * 64 + o] = tot1 - run1;
            d_off2[(b * NCH + ch) * 64 + o] = run2;
            run2 += v2[u];
        }
        if (lane == 0) {
            d_S1[((size_t)b * N1_ + N_) * C_ + o] = 0.f;
            d_S2[((size_t)b * N1_ + N_) * C_ + o] = (float)tot2;
        }
    }
    gsync();

    // ---------------- P6: write full S1/S2 arrays ----------------------------
    for (int task = bid; task < 512; task += GRID)
        scanC_task(sm.sc, task >> 7, task & 127);
    gsync();

    // ---------------- P7: final attention output -----------------------------
    {
        int b = bid >> 5, i0 = (bid & 31) * 128;
        for (int t = tid; t < N_; t += TPB) sm.fi.sq[t] = d_q[b * N_ + t];
        __syncthreads();
        int il = tid & 127;                  // node within tile (4x redundant)
        int qg = tid >> 7;                   // channel-quad group 0..3
        float aa = d_a[b * N_ + i0 + il];
        float tgt = -aa;
        int lo = 0, cnt = N_;
        while (cnt > 0) {
            int st = cnt >> 1;
            int mid = lo + st;
            if (sm.fi.sq[mid] < tgt) { lo = mid + 1; cnt -= st + 1; }
            else cnt = st;
        }
        int k = lo;
        float e1 = expf(aa), e2 = expf(0.2f * aa);
        float Z = e1 * d_T1[(size_t)b * N1_ + k] + e2 * d_T2[(size_t)b * N1_ + k];
        float w1 = e1 / Z, w2 = e2 / Z;
        const float4* s1p = (const float4*)&d_S1[((size_t)b * N1_ + k) * C_];
        const float4* s2p = (const float4*)&d_S2[((size_t)b * N1_ + k) * C_];
#pragma unroll
        for (int q = qg; q < 16; q += 4) {
            float4 A = s1p[q], Bv = s2p[q];
            sm.fi.sout[(q * 4 + 0) * 128 + il] = w1 * A.x + w2 * Bv.x;
            sm.fi.sout[(q * 4 + 1) * 128 + il] = w1 * A.y + w2 * Bv.y;
            sm.fi.sout[(q * 4 + 2) * 128 + il] = w1 * A.z + w2 * Bv.z;
            sm.fi.sout[(q * 4 + 3) * 128 + il] = w1 * A.w + w2 * Bv.w;
        }
        __syncthreads();
        float* outp = out + (size_t)b * C_ * N_;
        for (int idx = tid; idx < C_ * 128; idx += TPB) {
            int o = idx >> 7, ilx = idx & 127;
            outp[(size_t)o * N_ + i0 + ilx] = sm.fi.sout[idx];
        }
    }
    gsync();

    // ---------------- P8: C_k gemm (flag-gated, usually skipped) -------------
    if (d_flag) {
        for (int task = bid; task < 256; task += GRID) {
            int b = task >> 6;
            int i0 = (task & 63) * 64;
            int ti = tid >> 4, to = tid & 15;     // ti: 2 i-rows, to: 4 o-cols
            float acc[2][4];
#pragma unroll
            for (int ii = 0; ii < 2; ++ii)
#pragma unroll
                for (int oo = 0; oo < 4; ++oo) acc[ii][oo] = 0.f;

            for (int j0 = 0; j0 < N_; j0 += 64) {
                __syncthreads();
                for (int idx = tid; idx < 4096; idx += TPB) {
                    int ii = idx >> 6, jj = idx & 63;
                    sm.ck.Ash[ii][jj] = Ck[(size_t)(i0 + ii) * N_ + j0 + jj];
                }
                for (int idx = tid; idx < 4096; idx += TPB) {
                    int jj = idx >> 6, o = idx & 63;
                    sm.ck.Bsh[jj][o] = d_g[((size_t)b * N_ + j0 + jj) * C_ + o];
                }
                __syncthreads();
                for (int jj = 0; jj < 64; ++jj) {
                    float a0 = sm.ck.Ash[ti * 2 + 0][jj];
                    float a1 = sm.ck.Ash[ti * 2 + 1][jj];
                    float b0 = sm.ck.Bsh[jj][to * 4 + 0], b1 = sm.ck.Bsh[jj][to * 4 + 1];
                    float b2 = sm.ck.Bsh[jj][to * 4 + 2], b3 = sm.ck.Bsh[jj][to * 4 + 3];
                    acc[0][0] += a0 * b0; acc[0][1] += a0 * b1;
                    acc[0][2] += a0 * b2; acc[0][3] += a0 * b3;
                    acc[1][0] += a1 * b0; acc[1][1] += a1 * b1;
                    acc[1][2] += a1 * b2; acc[1][3] += a1 * b3;
                }
            }
            __syncthreads();
#pragma unroll
            for (int ii = 0; ii < 2; ++ii)
#pragma unroll
                for (int oo = 0; oo < 4; ++oo)
                    out[((size_t)b * C_ + to * 4 + oo) * N_ + i0 + ti * 2 + ii]
                        += acc[ii][oo];
        }
    }
}

// ---------------- launch ----------------
extern "C" void kernel_launch(void* const* d_in, const int* in_sizes, int n_in,
                              void* d_out, int out_size) {
    const float* x   = (const float*)d_in[0];
    const float* gw  = (const float*)d_in[1];
    const float* gb  = (const float*)d_in[2];
    const float* tw  = (const float*)d_in[3];
    const float* tb  = (const float*)d_in[4];
    const float* pw  = (const float*)d_in[5];
    const float* pb  = (const float*)d_in[6];
    const float* cp  = (const float*)d_in[7];
    const float* Ck  = (const float*)d_in[8];
    float* out = (float*)d_out;

    k_mega<<<GRID, TPB>>>(x, gw, gb, tw, tb, pw, pb, cp, Ck, out);
}